// round 15
// baseline (speedup 1.0000x reference)
#include <cuda_runtime.h>
#include <cstdint>

#define BQ    32
#define NN    512
#define MM    512
#define DFD   64
#define NDIAG 1023
#define NDPAD 1040          // padded (zero) so prefetch never clamps
#define TCH   8             // diagonals per chunk
#define TI    128           // dist tile rows (i)
#define TJ    128           // dist tile cols (j)
#define CPW   72            // active chunks per warp (trapezoid skip)

#define LOG2E 1.4426950408889634f
#define LN2   0.6931471805599453f
#define BIGS  1.4426950408889634e10f   // 1e10 * log2(e): self-maintaining in fp32
#define PROG_INF 100000

// Diagonal-major scaled distances: g_D[b][(i+j)][i] = log2e * ||x_i - y_j||^2.
// Zero-initialized; positions outside the valid band are never written.
__device__ float g_D[(size_t)BQ * NDPAD * NN];
// Per-batch, per-level (s = ty+tx) completed-tile counters for dist->dp gate.
__device__ int g_done[BQ][8];

// Tiles sorted by anti-diagonal level s = ty+tx (4x4 tile grid).
__device__ __constant__ signed char TILE_TY[16] =
    {0, 0,1, 0,1,2, 0,1,2,3, 1,2,3, 2,3, 3};
__device__ __constant__ signed char TILE_TX[16] =
    {0, 1,0, 2,1,0, 3,2,1,0, 3,2,1, 3,2, 3};
__device__ __constant__ int NS_CNT[7] = {1, 2, 3, 4, 3, 2, 1};

// ---------------------------------------------------------------------------
__device__ __forceinline__ uint32_t smem_u32(const void* p) {
    return (uint32_t)__cvta_generic_to_shared(p);
}
__device__ __forceinline__ void st_release_cta(uint32_t addr, int v) {
    asm volatile("st.release.cta.shared.b32 [%0], %1;" :: "r"(addr), "r"(v) : "memory");
}
__device__ __forceinline__ int ld_acquire_cta(uint32_t addr) {
    int v;
    asm volatile("ld.acquire.cta.shared.b32 %0, [%1];" : "=r"(v) : "r"(addr) : "memory");
    return v;
}
__device__ __forceinline__ int ld_acquire_gpu(const int* p) {
    int v;
    asm volatile("ld.acquire.gpu.global.b32 %0, [%1];" : "=r"(v) : "l"(p) : "memory");
    return v;
}
__device__ __forceinline__ float ex2(float x) {
    float r; asm("ex2.approx.f32 %0, %1;" : "=f"(r) : "f"(x)); return r;
}
__device__ __forceinline__ float lg2(float x) {
    float r; asm("lg2.approx.f32 %0, %1;" : "=f"(r) : "f"(x)); return r;
}

// ---------------------------------------------------------------------------
// Kernel 0: reset the dist->dp gate counters (graph node before the fork).
// ---------------------------------------------------------------------------
__global__ void init_done() {
    ((int*)g_done)[threadIdx.x] = 0;   // 256 = BQ*8 ints
}

// ---------------------------------------------------------------------------
// Kernel 1: pairwise squared distances (Gram form, FFMA), scaled by log2e,
// diagonal-major output. blockIdx.x = batch, blockIdx.y = s-sorted tile so
// low-level tiles across ALL batches schedule first. After writeback, the
// tile publishes into g_done[b][s].
// ---------------------------------------------------------------------------
__global__ void dist_kernel(const float* __restrict__ X,
                            const float* __restrict__ Y) {
    extern __shared__ float sm[];      // Xs|Ys, reused as Dt
    __shared__ float xx[TI], yy[TJ];
    float* Xs = sm;                    // [128][65]
    float* Ys = sm + TI * 65;          // [128][65]

    const int b    = blockIdx.x;
    const int tile = blockIdx.y;
    const int ty   = TILE_TY[tile];
    const int tx_t = TILE_TX[tile];
    const int s_lv = ty + tx_t;
    const int i0   = ty * TI;
    const int j0   = tx_t * TJ;
    const int tid  = threadIdx.x;

    const float4* Xb = (const float4*)(X + ((size_t)b * NN + i0) * DFD);
    const float4* Yb = (const float4*)(Y + ((size_t)b * MM + j0) * DFD);

    #pragma unroll
    for (int idx = tid; idx < TI * 16; idx += 256) {
        int r = idx >> 4, c4 = idx & 15;
        float4 v = Xb[r * 16 + c4];
        float* dst = &Xs[r * 65 + c4 * 4];
        dst[0] = v.x; dst[1] = v.y; dst[2] = v.z; dst[3] = v.w;
    }
    #pragma unroll
    for (int idx = tid; idx < TJ * 16; idx += 256) {
        int r = idx >> 4, c4 = idx & 15;
        float4 v = Yb[r * 16 + c4];
        float* dst = &Ys[r * 65 + c4 * 4];
        dst[0] = v.x; dst[1] = v.y; dst[2] = v.z; dst[3] = v.w;
    }
    __syncthreads();

    if (tid < TI + TJ) {
        const float* row = (tid < TI) ? &Xs[tid * 65] : &Ys[(tid - TI) * 65];
        float s = 0.f;
        #pragma unroll 8
        for (int k = 0; k < DFD; k++) s = fmaf(row[k], row[k], s);
        s *= LOG2E;
        if (tid < TI) xx[tid] = s; else yy[tid - TI] = s;
    }
    __syncthreads();

    const int tx = tid & 15;
    const int tyy = tid >> 4;

    float acc[8][8];
    #pragma unroll
    for (int u = 0; u < 8; u++)
        #pragma unroll
        for (int v = 0; v < 8; v++) acc[u][v] = 0.f;

    #pragma unroll 2
    for (int k = 0; k < DFD; k++) {
        float xa[8], yb[8];
        #pragma unroll
        for (int u = 0; u < 8; u++) xa[u] = Xs[(tyy + 16 * u) * 65 + k];
        #pragma unroll
        for (int v = 0; v < 8; v++) yb[v] = Ys[(tx + 16 * v) * 65 + k];
        #pragma unroll
        for (int u = 0; u < 8; u++)
            #pragma unroll
            for (int v = 0; v < 8; v++)
                acc[u][v] = fmaf(xa[u], yb[v], acc[u][v]);
    }
    __syncthreads();

    float* Dt = sm;                    // pitch 130 -> conflict-free diagonals
    #pragma unroll
    for (int u = 0; u < 8; u++) {
        const float xv = xx[tyy + 16 * u];
        #pragma unroll
        for (int v = 0; v < 8; v++)
            Dt[(tyy + 16 * u) * 130 + (tx + 16 * v)] =
                fmaf(-2.0f * LOG2E, acc[u][v], xv + yy[tx + 16 * v]);
    }
    __syncthreads();

    const int warp = tid >> 5, lane = tid & 31;
    const size_t base = (size_t)b * NDPAD * NN;
    for (int dl = warp; dl < TI + TJ - 1; dl += 8) {
        int lo = dl - (TJ - 1); if (lo < 0) lo = 0;
        int hi = dl;            if (hi > TI - 1) hi = TI - 1;
        for (int ii = lo + lane; ii <= hi; ii += 32) {
            int gi = i0 + ii;
            int gj = j0 + dl - ii;
            g_D[base + (size_t)(gi + gj) * NN + gi] = Dt[ii * 130 + (dl - ii)];
        }
    }

    // Publish: tile complete.
    __threadfence();
    __syncthreads();
    if (tid == 0) atomicAdd(&g_done[b][s_lv], 1);
}

// ---------------------------------------------------------------------------
// Soft-min cell, log2 domain, (p,q) presorted, late input last.
// ---------------------------------------------------------------------------
__device__ __forceinline__ float cell(float p, float q, float late, float Dv) {
    const float m   = fminf(p, late);
    const float mid = fminf(q, fmaxf(p, late));
    const float top = fmaxf(q, late);
    const float s   = 1.0f + ex2(m - mid) + ex2(m - top);
    return Dv + m - lg2(s);
}

// ---------------------------------------------------------------------------
// Kernel 2: warp-pipelined wavefront with trapezoid skip (R13) + D-gate.
// Runs CONCURRENTLY with dist: before loading D slots for a chunk, each warp
// ensures all dist tile-levels covering those diagonals have published.
// ---------------------------------------------------------------------------
__global__ void __launch_bounds__(256, 1)
dp_kernel(const int* __restrict__ X_len, const int* __restrict__ Y_len,
          float* __restrict__ out) {
    __shared__ float edge[8][1032];    // edge[w][d] = R'[d][64(w+1)]
    __shared__ float nb[8][32];        // per-warp lane ring of cur_hi
    __shared__ int   prog[8];

    const int b    = blockIdx.x;
    const int tid  = threadIdx.x;
    const int w    = tid >> 5;
    const int lane = tid & 31;
    const int i_lo = 2 * tid + 1;
    const int i_hi = i_lo + 1;

    const int xl  = X_len[b];
    const int tot = xl + Y_len[b];
    const bool wantlo = (xl == i_lo);
    const bool wanthi = (xl == i_hi);
    const bool isl0   = (lane == 0);
    const bool isl31  = (lane == 31);
    const int  nlane  = (lane == 0) ? 31 : lane - 1;

    for (int idx = tid; idx < 8 * 1032; idx += 256)
        ((float*)edge)[idx] = BIGS;
    if (tid < 8) prog[tid] = 1;
    nb[w][lane] = BIGS;
    __syncthreads();                    // the only CTA barrier

    const uint32_t prog_self = smem_u32(&prog[w]);
    const uint32_t prog_prev = smem_u32(&prog[(w == 0) ? 0 : w - 1]);

    const float2* Dp = (const float2*)(g_D + (size_t)b * NDPAD * NN) + tid;

    const int c0 = 8 * w;
    const int c1 = 8 * w + CPW - 1;

    // D-availability gate: all levels s with 128*s <= dd_max must be done.
    int next_s = 0;
    #define ENSURE_D(dd_max)                                                  \
        while (next_s < 7 && 128 * next_s <= (dd_max)) {                      \
            const int need_ = NS_CNT[next_s];                                 \
            while (ld_acquire_gpu(&g_done[b][next_s]) < need_)                \
                __nanosleep(128);                                             \
            next_s++;                                                         \
        }

    ENSURE_D(TCH * c0 + 7);
    float2 Dc[TCH];
    #pragma unroll
    for (int k = 0; k < TCH; ++k)
        Dc[k] = Dp[(size_t)(TCH * c0 + k) * 256];

    float r1_lo = BIGS, r1_hi = BIGS;
    float p_lo = (tid == 0) ? 0.0f : BIGS, q_lo = BIGS;
    float p_hi = BIGS, q_hi = BIGS;
    float res = 0.0f;

    for (int c = c0; c <= c1; ++c) {
        const int d0 = 2 + TCH * c;

        // Gate + prefetch next chunk's D.
        ENSURE_D(TCH * (c + 1) + 7);
        float2 Dn[TCH];
        #pragma unroll
        for (int k = 0; k < TCH; ++k)
            Dn[k] = Dp[(size_t)(TCH * (c + 1) + k) * 256];

        float e[TCH];
        if (w > 0) {
            const int needed = d0 + TCH - 2;
            while (ld_acquire_cta(prog_prev) < needed) __nanosleep(64);
            #pragma unroll
            for (int k = 0; k < TCH; ++k) e[k] = edge[w - 1][d0 - 1 + k];
        } else {
            #pragma unroll
            for (int k = 0; k < TCH; ++k) e[k] = BIGS;
        }

        if ((unsigned)(tot - d0) < TCH) {
            #pragma unroll
            for (int k = 0; k < TCH; ++k) {
                const int d = d0 + k;
                const float nbv = nb[w][nlane];

                const float cur_hi = cell(p_hi, q_hi, r1_hi, Dc[k].y);
                nb[w][lane] = cur_hi;
                if (isl31) edge[w][d] = cur_hi;

                const float tmp = isl0 ? e[k] : nbv;
                const float cur_lo = cell(p_lo, q_lo, tmp, Dc[k].x);

                if (d == tot)
                    res = wantlo ? cur_lo : (wanthi ? cur_hi : res);

                p_hi = fminf(r1_lo, cur_lo);
                q_hi = fmaxf(r1_lo, cur_lo);
                p_lo = fminf(tmp, cur_lo);
                q_lo = fmaxf(tmp, cur_lo);
                r1_lo = cur_lo;
                r1_hi = cur_hi;
            }
        } else {
            #pragma unroll
            for (int k = 0; k < TCH; ++k) {
                const int d = d0 + k;
                const float nbv = nb[w][nlane];

                const float cur_hi = cell(p_hi, q_hi, r1_hi, Dc[k].y);
                nb[w][lane] = cur_hi;
                if (isl31) edge[w][d] = cur_hi;

                const float tmp = isl0 ? e[k] : nbv;
                const float cur_lo = cell(p_lo, q_lo, tmp, Dc[k].x);

                p_hi = fminf(r1_lo, cur_lo);
                q_hi = fmaxf(r1_lo, cur_lo);
                p_lo = fminf(tmp, cur_lo);
                q_lo = fmaxf(tmp, cur_lo);
                r1_lo = cur_lo;
                r1_hi = cur_hi;
            }
        }

        if (w < 7 && isl31)
            st_release_cta(prog_self, d0 + TCH - 1);   // orders edge STS

        #pragma unroll
        for (int k = 0; k < TCH; ++k) Dc[k] = Dn[k];
    }

    if (w < 7 && isl31)
        st_release_cta(prog_self, PROG_INF);

    if (wantlo | wanthi) out[b] = res * LN2;
    #undef ENSURE_D
}

// ---------------------------------------------------------------------------
extern "C" void kernel_launch(void* const* d_in, const int* in_sizes, int n_in,
                              void* d_out, int out_size) {
    const float* X     = (const float*)d_in[0];
    const float* Y     = (const float*)d_in[1];
    const int*   X_len = (const int*)d_in[2];
    const int*   Y_len = (const int*)d_in[3];
    float*       out   = (float*)d_out;

    const int dist_smem = (TI * 65 + TJ * 65) * 4;   // 66560 B

    static bool inited = false;
    static cudaStream_t s2;
    static cudaEvent_t ev_fork, ev_join;
    if (!inited) {
        cudaFuncSetAttribute(dist_kernel,
                             cudaFuncAttributeMaxDynamicSharedMemorySize,
                             dist_smem);
        cudaStreamCreateWithFlags(&s2, cudaStreamNonBlocking);
        cudaEventCreateWithFlags(&ev_fork, cudaEventDisableTiming);
        cudaEventCreateWithFlags(&ev_join, cudaEventDisableTiming);
        inited = true;
    }

    // Fork: init gate counters, then run dist (stream s2) || dp (stream 0).
    init_done<<<1, 256>>>();
    cudaEventRecord(ev_fork, 0);
    cudaStreamWaitEvent(s2, ev_fork, 0);

    dist_kernel<<<dim3(BQ, 16, 1), 256, dist_smem, s2>>>(X, Y);
    cudaEventRecord(ev_join, s2);

    dp_kernel<<<BQ, 256>>>(X_len, Y_len, out);

    // Join so downstream ops on the capture stream depend on dist too.
    cudaStreamWaitEvent(0, ev_join, 0);
}

// round 16
// speedup vs baseline: 1.0609x; 1.0609x over previous
#include <cuda_runtime.h>
#include <cstdint>

#define BQ    32
#define NN    512
#define MM    512
#define DFD   64
#define NDIAG 1023
#define NDPAD 1040          // padded (zero) so prefetch never clamps
#define TCH   8             // diagonals per chunk
#define TI    128           // dist tile rows (i)
#define TJ    128           // dist tile cols (j)
#define CPW   72            // active chunks per warp (trapezoid skip)

// dp dynamic smem: real state ~34 KB, padded to 170 KB so no dist CTA
// (67.5 KB) can co-reside on a dp SM -> SM isolation for the overlap.
#define DPSMEM 174080

#define LOG2E 1.4426950408889634f
#define LN2   0.6931471805599453f
#define BIGS  1.4426950408889634e10f   // 1e10 * log2(e): self-maintaining in fp32
#define PROG_INF 100000

// Diagonal-major scaled distances: g_D[b][(i+j)][i] = log2e * ||x_i - y_j||^2.
// Zero-initialized; positions outside the valid band are never written.
__device__ float g_D[(size_t)BQ * NDPAD * NN];
// Per-batch, per-level (s = ty+tx) completed-tile counters for dist->dp gate.
__device__ int g_done[BQ][8];

// Tiles sorted by anti-diagonal level s = ty+tx (4x4 tile grid).
__device__ __constant__ signed char TILE_TY[16] =
    {0, 0,1, 0,1,2, 0,1,2,3, 1,2,3, 2,3, 3};
__device__ __constant__ signed char TILE_TX[16] =
    {0, 1,0, 2,1,0, 3,2,1,0, 3,2,1, 3,2, 3};
__device__ __constant__ int NS_CNT[7] = {1, 2, 3, 4, 3, 2, 1};

// ---------------------------------------------------------------------------
__device__ __forceinline__ uint32_t smem_u32(const void* p) {
    return (uint32_t)__cvta_generic_to_shared(p);
}
__device__ __forceinline__ void st_release_cta(uint32_t addr, int v) {
    asm volatile("st.release.cta.shared.b32 [%0], %1;" :: "r"(addr), "r"(v) : "memory");
}
__device__ __forceinline__ int ld_acquire_cta(uint32_t addr) {
    int v;
    asm volatile("ld.acquire.cta.shared.b32 %0, [%1];" : "=r"(v) : "r"(addr) : "memory");
    return v;
}
__device__ __forceinline__ int ld_acquire_gpu(const int* p) {
    int v;
    asm volatile("ld.acquire.gpu.global.b32 %0, [%1];" : "=r"(v) : "l"(p) : "memory");
    return v;
}
__device__ __forceinline__ float ex2(float x) {
    float r; asm("ex2.approx.f32 %0, %1;" : "=f"(r) : "f"(x)); return r;
}
__device__ __forceinline__ float lg2(float x) {
    float r; asm("lg2.approx.f32 %0, %1;" : "=f"(r) : "f"(x)); return r;
}

// ---------------------------------------------------------------------------
// Kernel 0: reset the dist->dp gate counters.
// ---------------------------------------------------------------------------
__global__ void init_done() {
    ((int*)g_done)[threadIdx.x] = 0;   // 256 = BQ*8 ints
}

// ---------------------------------------------------------------------------
// Kernel 1: pairwise squared distances (Gram form, FFMA), scaled by log2e,
// diagonal-major output. blockIdx.x = batch, blockIdx.y = s-sorted tile so
// low-level tiles across ALL batches schedule first. Publishes g_done[b][s].
// Runs on the 116 SMs not reserved by dp (smem exclusion).
// ---------------------------------------------------------------------------
__global__ void dist_kernel(const float* __restrict__ X,
                            const float* __restrict__ Y) {
    extern __shared__ float sm[];      // Xs|Ys, reused as Dt
    __shared__ float xx[TI], yy[TJ];
    float* Xs = sm;                    // [128][65]
    float* Ys = sm + TI * 65;          // [128][65]

    const int b    = blockIdx.x;
    const int tile = blockIdx.y;
    const int ty   = TILE_TY[tile];
    const int tx_t = TILE_TX[tile];
    const int s_lv = ty + tx_t;
    const int i0   = ty * TI;
    const int j0   = tx_t * TJ;
    const int tid  = threadIdx.x;

    const float4* Xb = (const float4*)(X + ((size_t)b * NN + i0) * DFD);
    const float4* Yb = (const float4*)(Y + ((size_t)b * MM + j0) * DFD);

    #pragma unroll
    for (int idx = tid; idx < TI * 16; idx += 256) {
        int r = idx >> 4, c4 = idx & 15;
        float4 v = Xb[r * 16 + c4];
        float* dst = &Xs[r * 65 + c4 * 4];
        dst[0] = v.x; dst[1] = v.y; dst[2] = v.z; dst[3] = v.w;
    }
    #pragma unroll
    for (int idx = tid; idx < TJ * 16; idx += 256) {
        int r = idx >> 4, c4 = idx & 15;
        float4 v = Yb[r * 16 + c4];
        float* dst = &Ys[r * 65 + c4 * 4];
        dst[0] = v.x; dst[1] = v.y; dst[2] = v.z; dst[3] = v.w;
    }
    __syncthreads();

    if (tid < TI + TJ) {
        const float* row = (tid < TI) ? &Xs[tid * 65] : &Ys[(tid - TI) * 65];
        float s = 0.f;
        #pragma unroll 8
        for (int k = 0; k < DFD; k++) s = fmaf(row[k], row[k], s);
        s *= LOG2E;
        if (tid < TI) xx[tid] = s; else yy[tid - TI] = s;
    }
    __syncthreads();

    const int tx = tid & 15;
    const int tyy = tid >> 4;

    float acc[8][8];
    #pragma unroll
    for (int u = 0; u < 8; u++)
        #pragma unroll
        for (int v = 0; v < 8; v++) acc[u][v] = 0.f;

    #pragma unroll 2
    for (int k = 0; k < DFD; k++) {
        float xa[8], yb[8];
        #pragma unroll
        for (int u = 0; u < 8; u++) xa[u] = Xs[(tyy + 16 * u) * 65 + k];
        #pragma unroll
        for (int v = 0; v < 8; v++) yb[v] = Ys[(tx + 16 * v) * 65 + k];
        #pragma unroll
        for (int u = 0; u < 8; u++)
            #pragma unroll
            for (int v = 0; v < 8; v++)
                acc[u][v] = fmaf(xa[u], yb[v], acc[u][v]);
    }
    __syncthreads();

    float* Dt = sm;                    // pitch 130 -> conflict-free diagonals
    #pragma unroll
    for (int u = 0; u < 8; u++) {
        const float xv = xx[tyy + 16 * u];
        #pragma unroll
        for (int v = 0; v < 8; v++)
            Dt[(tyy + 16 * u) * 130 + (tx + 16 * v)] =
                fmaf(-2.0f * LOG2E, acc[u][v], xv + yy[tx + 16 * v]);
    }
    __syncthreads();

    const int warp = tid >> 5, lane = tid & 31;
    const size_t base = (size_t)b * NDPAD * NN;
    for (int dl = warp; dl < TI + TJ - 1; dl += 8) {
        int lo = dl - (TJ - 1); if (lo < 0) lo = 0;
        int hi = dl;            if (hi > TI - 1) hi = TI - 1;
        for (int ii = lo + lane; ii <= hi; ii += 32) {
            int gi = i0 + ii;
            int gj = j0 + dl - ii;
            g_D[base + (size_t)(gi + gj) * NN + gi] = Dt[ii * 130 + (dl - ii)];
        }
    }

    // Publish: tile complete.
    __threadfence();
    __syncthreads();
    if (tid == 0) atomicAdd(&g_done[b][s_lv], 1);
}

// ---------------------------------------------------------------------------
// Soft-min cell, log2 domain, (p,q) presorted, late input last.
// ---------------------------------------------------------------------------
__device__ __forceinline__ float cell(float p, float q, float late, float Dv) {
    const float m   = fminf(p, late);
    const float mid = fminf(q, fmaxf(p, late));
    const float top = fmaxf(q, late);
    const float s   = 1.0f + ex2(m - mid) + ex2(m - top);
    return Dv + m - lg2(s);
}

// ---------------------------------------------------------------------------
// Kernel 2: warp-pipelined wavefront with trapezoid skip + D-gate.
// Dynamic smem padded to 170 KB -> each dp CTA owns its SM exclusively
// (no dist CTA fits alongside), so the overlap can't steal dp cycles.
// ---------------------------------------------------------------------------
__global__ void __launch_bounds__(256, 1)
dp_kernel(const int* __restrict__ X_len, const int* __restrict__ Y_len,
          float* __restrict__ out) {
    extern __shared__ float dsm[];
    float (*edge)[1032] = (float (*)[1032])dsm;                 // [8][1032]
    float (*nb)[32]     = (float (*)[32])(dsm + 8 * 1032);      // [8][32]
    int*  prog          = (int*)(dsm + 8 * 1032 + 8 * 32);

    const int b    = blockIdx.x;
    const int tid  = threadIdx.x;
    const int w    = tid >> 5;
    const int lane = tid & 31;
    const int i_lo = 2 * tid + 1;
    const int i_hi = i_lo + 1;

    const int xl  = X_len[b];
    const int tot = xl + Y_len[b];
    const bool wantlo = (xl == i_lo);
    const bool wanthi = (xl == i_hi);
    const bool isl0   = (lane == 0);
    const bool isl31  = (lane == 31);
    const int  nlane  = (lane == 0) ? 31 : lane - 1;

    for (int idx = tid; idx < 8 * 1032; idx += 256)
        ((float*)edge)[idx] = BIGS;
    if (tid < 8) prog[tid] = 1;
    nb[w][lane] = BIGS;
    __syncthreads();                    // the only CTA barrier

    const uint32_t prog_self = smem_u32(&prog[w]);
    const uint32_t prog_prev = smem_u32(&prog[(w == 0) ? 0 : w - 1]);

    const float2* Dp = (const float2*)(g_D + (size_t)b * NDPAD * NN) + tid;

    const int c0 = 8 * w;
    const int c1 = 8 * w + CPW - 1;

    // D-availability gate: all levels s with 128*s <= dd_max must be done.
    int next_s = 0;
    #define ENSURE_D(dd_max)                                                  \
        while (next_s < 7 && 128 * next_s <= (dd_max)) {                      \
            const int need_ = NS_CNT[next_s];                                 \
            while (ld_acquire_gpu(&g_done[b][next_s]) < need_)                \
                __nanosleep(128);                                             \
            next_s++;                                                         \
        }

    ENSURE_D(TCH * c0 + 7);
    float2 Dc[TCH];
    #pragma unroll
    for (int k = 0; k < TCH; ++k)
        Dc[k] = Dp[(size_t)(TCH * c0 + k) * 256];

    float r1_lo = BIGS, r1_hi = BIGS;
    float p_lo = (tid == 0) ? 0.0f : BIGS, q_lo = BIGS;
    float p_hi = BIGS, q_hi = BIGS;
    float res = 0.0f;

    for (int c = c0; c <= c1; ++c) {
        const int d0 = 2 + TCH * c;

        // Gate + prefetch next chunk's D.
        ENSURE_D(TCH * (c + 1) + 7);
        float2 Dn[TCH];
        #pragma unroll
        for (int k = 0; k < TCH; ++k)
            Dn[k] = Dp[(size_t)(TCH * (c + 1) + k) * 256];

        float e[TCH];
        if (w > 0) {
            const int needed = d0 + TCH - 2;
            while (ld_acquire_cta(prog_prev) < needed) __nanosleep(64);
            #pragma unroll
            for (int k = 0; k < TCH; ++k) e[k] = edge[w - 1][d0 - 1 + k];
        } else {
            #pragma unroll
            for (int k = 0; k < TCH; ++k) e[k] = BIGS;
        }

        if ((unsigned)(tot - d0) < TCH) {
            #pragma unroll
            for (int k = 0; k < TCH; ++k) {
                const int d = d0 + k;
                const float nbv = nb[w][nlane];

                const float cur_hi = cell(p_hi, q_hi, r1_hi, Dc[k].y);
                nb[w][lane] = cur_hi;
                if (isl31) edge[w][d] = cur_hi;

                const float tmp = isl0 ? e[k] : nbv;
                const float cur_lo = cell(p_lo, q_lo, tmp, Dc[k].x);

                if (d == tot)
                    res = wantlo ? cur_lo : (wanthi ? cur_hi : res);

                p_hi = fminf(r1_lo, cur_lo);
                q_hi = fmaxf(r1_lo, cur_lo);
                p_lo = fminf(tmp, cur_lo);
                q_lo = fmaxf(tmp, cur_lo);
                r1_lo = cur_lo;
                r1_hi = cur_hi;
            }
        } else {
            #pragma unroll
            for (int k = 0; k < TCH; ++k) {
                const int d = d0 + k;
                const float nbv = nb[w][nlane];

                const float cur_hi = cell(p_hi, q_hi, r1_hi, Dc[k].y);
                nb[w][lane] = cur_hi;
                if (isl31) edge[w][d] = cur_hi;

                const float tmp = isl0 ? e[k] : nbv;
                const float cur_lo = cell(p_lo, q_lo, tmp, Dc[k].x);

                p_hi = fminf(r1_lo, cur_lo);
                q_hi = fmaxf(r1_lo, cur_lo);
                p_lo = fminf(tmp, cur_lo);
                q_lo = fmaxf(tmp, cur_lo);
                r1_lo = cur_lo;
                r1_hi = cur_hi;
            }
        }

        if (w < 7 && isl31)
            st_release_cta(prog_self, d0 + TCH - 1);   // orders edge STS

        #pragma unroll
        for (int k = 0; k < TCH; ++k) Dc[k] = Dn[k];
    }

    if (w < 7 && isl31)
        st_release_cta(prog_self, PROG_INF);

    if (wantlo | wanthi) out[b] = res * LN2;
    #undef ENSURE_D
}

// ---------------------------------------------------------------------------
extern "C" void kernel_launch(void* const* d_in, const int* in_sizes, int n_in,
                              void* d_out, int out_size) {
    const float* X     = (const float*)d_in[0];
    const float* Y     = (const float*)d_in[1];
    const int*   X_len = (const int*)d_in[2];
    const int*   Y_len = (const int*)d_in[3];
    float*       out   = (float*)d_out;

    const int dist_smem = (TI * 65 + TJ * 65) * 4;   // 66560 B

    static bool inited = false;
    static cudaStream_t s2;
    static cudaEvent_t ev_fork, ev_join;
    if (!inited) {
        cudaFuncSetAttribute(dist_kernel,
                             cudaFuncAttributeMaxDynamicSharedMemorySize,
                             dist_smem);
        cudaFuncSetAttribute(dp_kernel,
                             cudaFuncAttributeMaxDynamicSharedMemorySize,
                             DPSMEM);
        cudaStreamCreateWithFlags(&s2, cudaStreamNonBlocking);
        cudaEventCreateWithFlags(&ev_fork, cudaEventDisableTiming);
        cudaEventCreateWithFlags(&ev_join, cudaEventDisableTiming);
        inited = true;
    }

    // init -> fork; dp enqueued FIRST (its 32 CTAs claim SMs before dist's
    // wave); dist fills the remaining 116 SMs (smem exclusion).
    init_done<<<1, 256>>>();
    cudaEventRecord(ev_fork, 0);
    cudaStreamWaitEvent(s2, ev_fork, 0);

    dp_kernel<<<BQ, 256, DPSMEM>>>(X_len, Y_len, out);

    dist_kernel<<<dim3(BQ, 16, 1), 256, dist_smem, s2>>>(X, Y);
    cudaEventRecord(ev_join, s2);

    // Join so downstream ops on the capture stream depend on dist too.
    cudaStreamWaitEvent(0, ev_join, 0);
}

// round 17
// speedup vs baseline: 1.1411x; 1.0757x over previous
#include <cuda_runtime.h>
#include <cstdint>

#define BQ    32
#define NN    512
#define MM    512
#define DFD   64
#define NDIAG 1023
#define NDPAD 1040          // padded (zero) so prefetch never clamps
#define TCH   8             // diagonals per chunk
#define TI    128           // dist tile rows (i)
#define TJ    128           // dist tile cols (j)
#define CPW   72            // active chunks per warp (trapezoid skip)

#define LOG2E 1.4426950408889634f
#define LN2   0.6931471805599453f
#define BIGS  1.4426950408889634e10f   // 1e10 * log2(e): self-maintaining in fp32
#define PROG_INF 100000

// Diagonal-major scaled distances: g_D[b][(i+j)][i] = log2e * ||x_i - y_j||^2.
// Zero-initialized; positions outside the valid band are never written.
__device__ float g_D[(size_t)BQ * NDPAD * NN];

// ---------------------------------------------------------------------------
__device__ __forceinline__ uint32_t smem_u32(const void* p) {
    return (uint32_t)__cvta_generic_to_shared(p);
}
__device__ __forceinline__ void st_release_cta(uint32_t addr, int v) {
    asm volatile("st.release.cta.shared.b32 [%0], %1;" :: "r"(addr), "r"(v) : "memory");
}
__device__ __forceinline__ int ld_acquire_cta(uint32_t addr) {
    int v;
    asm volatile("ld.acquire.cta.shared.b32 %0, [%1];" : "=r"(v) : "r"(addr) : "memory");
    return v;
}
__device__ __forceinline__ float ex2(float x) {
    float r; asm("ex2.approx.f32 %0, %1;" : "=f"(r) : "f"(x)); return r;
}
__device__ __forceinline__ float lg2(float x) {
    float r; asm("lg2.approx.f32 %0, %1;" : "=f"(r) : "f"(x)); return r;
}

// ---------------------------------------------------------------------------
// Kernel 1: pairwise squared distances (Gram form, FFMA), scaled by log2e,
// diagonal-major output. 128x128 tile per CTA, 8x8 register tile per thread.
// ---------------------------------------------------------------------------
__global__ void dist_kernel(const float* __restrict__ X,
                            const float* __restrict__ Y) {
    extern __shared__ float sm[];      // Xs|Ys, reused as Dt
    __shared__ float xx[TI], yy[TJ];
    float* Xs = sm;                    // [128][65]
    float* Ys = sm + TI * 65;          // [128][65]

    const int b  = blockIdx.z;
    const int i0 = blockIdx.y * TI;
    const int j0 = blockIdx.x * TJ;
    const int tid = threadIdx.x;

    const float4* Xb = (const float4*)(X + ((size_t)b * NN + i0) * DFD);
    const float4* Yb = (const float4*)(Y + ((size_t)b * MM + j0) * DFD);

    #pragma unroll
    for (int idx = tid; idx < TI * 16; idx += 256) {
        int r = idx >> 4, c4 = idx & 15;
        float4 v = Xb[r * 16 + c4];
        float* dst = &Xs[r * 65 + c4 * 4];
        dst[0] = v.x; dst[1] = v.y; dst[2] = v.z; dst[3] = v.w;
    }
    #pragma unroll
    for (int idx = tid; idx < TJ * 16; idx += 256) {
        int r = idx >> 4, c4 = idx & 15;
        float4 v = Yb[r * 16 + c4];
        float* dst = &Ys[r * 65 + c4 * 4];
        dst[0] = v.x; dst[1] = v.y; dst[2] = v.z; dst[3] = v.w;
    }
    __syncthreads();

    if (tid < TI + TJ) {
        const float* row = (tid < TI) ? &Xs[tid * 65] : &Ys[(tid - TI) * 65];
        float s = 0.f;
        #pragma unroll 8
        for (int k = 0; k < DFD; k++) s = fmaf(row[k], row[k], s);
        s *= LOG2E;
        if (tid < TI) xx[tid] = s; else yy[tid - TI] = s;
    }
    __syncthreads();

    const int tx = tid & 15;
    const int ty = tid >> 4;

    float acc[8][8];
    #pragma unroll
    for (int u = 0; u < 8; u++)
        #pragma unroll
        for (int v = 0; v < 8; v++) acc[u][v] = 0.f;

    #pragma unroll 2
    for (int k = 0; k < DFD; k++) {
        float xa[8], yb[8];
        #pragma unroll
        for (int u = 0; u < 8; u++) xa[u] = Xs[(ty + 16 * u) * 65 + k];
        #pragma unroll
        for (int v = 0; v < 8; v++) yb[v] = Ys[(tx + 16 * v) * 65 + k];
        #pragma unroll
        for (int u = 0; u < 8; u++)
            #pragma unroll
            for (int v = 0; v < 8; v++)
                acc[u][v] = fmaf(xa[u], yb[v], acc[u][v]);
    }
    __syncthreads();

    float* Dt = sm;                    // pitch 130 -> conflict-free diagonals
    #pragma unroll
    for (int u = 0; u < 8; u++) {
        const float xv = xx[ty + 16 * u];
        #pragma unroll
        for (int v = 0; v < 8; v++)
            Dt[(ty + 16 * u) * 130 + (tx + 16 * v)] =
                fmaf(-2.0f * LOG2E, acc[u][v], xv + yy[tx + 16 * v]);
    }
    __syncthreads();

    const int warp = tid >> 5, lane = tid & 31;
    const size_t base = (size_t)b * NDPAD * NN;
    for (int dl = warp; dl < TI + TJ - 1; dl += 8) {
        int lo = dl - (TJ - 1); if (lo < 0) lo = 0;
        int hi = dl;            if (hi > TI - 1) hi = TI - 1;
        for (int ii = lo + lane; ii <= hi; ii += 32) {
            int gi = i0 + ii;
            int gj = j0 + dl - ii;
            g_D[base + (size_t)(gi + gj) * NN + gi] = Dt[ii * 130 + (dl - ii)];
        }
    }
}

// ---------------------------------------------------------------------------
// Soft-min cell, log2 domain, (p,q) presorted, late input last.
// ---------------------------------------------------------------------------
__device__ __forceinline__ float cell(float p, float q, float late, float Dv) {
    const float m   = fminf(p, late);
    const float mid = fminf(q, fmaxf(p, late));
    const float top = fmaxf(q, late);
    const float s   = 1.0f + ex2(m - mid) + ex2(m - top);
    return Dv + m - lg2(s);
}

// ---------------------------------------------------------------------------
// Kernel 2: warp-pipelined wavefront with trapezoid skip (R13) + SMSP-AWARE
// WARP PERMUTATION. HW maps warp->SMSP as wid%4; pipeline-adjacent stages
// are co-active 88% of the time (lag 9 chunk-steps) while w,w+4 overlap only
// 50%. Logical position w = (wid%4)*2 + wid/4 puts adjacent stages on the
// SAME SMSP so each warp's chain stalls are hidden by its pipeline neighbor.
// All protocol state (rows, D, edge, prog, trapezoid range) keys off logical w.
// ---------------------------------------------------------------------------
__global__ void __launch_bounds__(256, 1)
dp_kernel(const int* __restrict__ X_len, const int* __restrict__ Y_len,
          float* __restrict__ out) {
    __shared__ float edge[8][1032];    // edge[w][d] = R'[d][64(w+1)]
    __shared__ float nb[8][32];        // per-warp lane ring of cur_hi
    __shared__ int   prog[8];

    const int b    = blockIdx.x;
    const int tid  = threadIdx.x;
    const int wid  = tid >> 5;
    const int lane = tid & 31;
    // Logical pipeline position: adjacent positions share an SMSP.
    const int w    = ((wid & 3) << 1) | (wid >> 2);
    const int vtid = 32 * w + lane;    // virtual thread index (row ordering)
    const int i_lo = 2 * vtid + 1;
    const int i_hi = i_lo + 1;

    const int xl  = X_len[b];
    const int tot = xl + Y_len[b];
    const bool wantlo = (xl == i_lo);
    const bool wanthi = (xl == i_hi);
    const bool isl0   = (lane == 0);
    const bool isl31  = (lane == 31);
    const int  nlane  = (lane == 0) ? 31 : lane - 1;

    // Pre-init the ENTIRE edge history to BIGS (covers never-written slots).
    for (int idx = tid; idx < 8 * 1032; idx += 256)
        ((float*)edge)[idx] = BIGS;
    if (tid < 8) prog[tid] = 1;
    nb[w][lane] = BIGS;
    __syncthreads();                    // the only CTA barrier

    const uint32_t prog_self = smem_u32(&prog[w]);
    const uint32_t prog_prev = smem_u32(&prog[(w == 0) ? 0 : w - 1]);

    const float2* Dp = (const float2*)(g_D + (size_t)b * NDPAD * NN) + vtid;

    // Active chunk range for this (logical) warp.
    const int c0 = 8 * w;
    const int c1 = 8 * w + CPW - 1;

    float2 Dc[TCH];
    #pragma unroll
    for (int k = 0; k < TCH; ++k)
        Dc[k] = Dp[(size_t)(TCH * c0 + k) * 256];

    float r1_lo = BIGS, r1_hi = BIGS;
    float p_lo = (vtid == 0) ? 0.0f : BIGS, q_lo = BIGS;
    float p_hi = BIGS, q_hi = BIGS;
    float res = 0.0f;

    for (int c = c0; c <= c1; ++c) {
        const int d0 = 2 + TCH * c;

        // Prefetch next chunk's D (padded slots; tail reads hit zero pad).
        float2 Dn[TCH];
        #pragma unroll
        for (int k = 0; k < TCH; ++k)
            Dn[k] = Dp[(size_t)(TCH * (c + 1) + k) * 256];

        // Acquire producer edges for this chunk (monotonic counter, backoff).
        float e[TCH];
        if (w > 0) {
            const int needed = d0 + TCH - 2;
            while (ld_acquire_cta(prog_prev) < needed) __nanosleep(64);
            #pragma unroll
            for (int k = 0; k < TCH; ++k) e[k] = edge[w - 1][d0 - 1 + k];
        } else {
            #pragma unroll
            for (int k = 0; k < TCH; ++k) e[k] = BIGS;
        }

        if ((unsigned)(tot - d0) < TCH) {
            // ---- capture body: the one chunk that can produce the output ----
            #pragma unroll
            for (int k = 0; k < TCH; ++k) {
                const int d = d0 + k;
                const float nbv = nb[w][nlane];

                const float cur_hi = cell(p_hi, q_hi, r1_hi, Dc[k].y);
                nb[w][lane] = cur_hi;
                if (isl31) edge[w][d] = cur_hi;

                const float tmp = isl0 ? e[k] : nbv;
                const float cur_lo = cell(p_lo, q_lo, tmp, Dc[k].x);

                if (d == tot)
                    res = wantlo ? cur_lo : (wanthi ? cur_hi : res);

                p_hi = fminf(r1_lo, cur_lo);
                q_hi = fmaxf(r1_lo, cur_lo);
                p_lo = fminf(tmp, cur_lo);
                q_lo = fmaxf(tmp, cur_lo);
                r1_lo = cur_lo;
                r1_hi = cur_hi;
            }
        } else {
            // ---- hot body ----
            #pragma unroll
            for (int k = 0; k < TCH; ++k) {
                const int d = d0 + k;
                const float nbv = nb[w][nlane];

                const float cur_hi = cell(p_hi, q_hi, r1_hi, Dc[k].y);
                nb[w][lane] = cur_hi;
                if (isl31) edge[w][d] = cur_hi;

                const float tmp = isl0 ? e[k] : nbv;
                const float cur_lo = cell(p_lo, q_lo, tmp, Dc[k].x);

                p_hi = fminf(r1_lo, cur_lo);
                q_hi = fmaxf(r1_lo, cur_lo);
                p_lo = fminf(tmp, cur_lo);
                q_lo = fmaxf(tmp, cur_lo);
                r1_lo = cur_lo;
                r1_hi = cur_hi;
            }
        }

        if (w < 7 && isl31)
            st_release_cta(prog_self, d0 + TCH - 1);   // orders edge STS

        #pragma unroll
        for (int k = 0; k < TCH; ++k) Dc[k] = Dn[k];
    }

    // Final publish: everything beyond this warp's active range is BIGS
    // (pre-initialized) — release "infinity" so consumers never wait.
    if (w < 7 && isl31)
        st_release_cta(prog_self, PROG_INF);

    if (wantlo | wanthi) out[b] = res * LN2;
}

// ---------------------------------------------------------------------------
extern "C" void kernel_launch(void* const* d_in, const int* in_sizes, int n_in,
                              void* d_out, int out_size) {
    const float* X     = (const float*)d_in[0];
    const float* Y     = (const float*)d_in[1];
    const int*   X_len = (const int*)d_in[2];
    const int*   Y_len = (const int*)d_in[3];
    float*       out   = (float*)d_out;

    const int dist_smem = (TI * 65 + TJ * 65) * 4;   // 66560 B
    static bool attr_set = false;
    if (!attr_set) {
        cudaFuncSetAttribute(dist_kernel,
                             cudaFuncAttributeMaxDynamicSharedMemorySize,
                             dist_smem);
        attr_set = true;
    }

    dist_kernel<<<dim3(MM / TJ, NN / TI, BQ), 256, dist_smem>>>(X, Y);
    dp_kernel<<<BQ, 256>>>(X_len, Y_len, out);
}